// round 9
// baseline (speedup 1.0000x reference)
#include <cuda_runtime.h>

#define NV 4096            // nodes per graph
#define NB 32              // batch size (== warp size, load-bearing)
#define BN (NV * NB)       // 131072
#define CH 8               // chunks over the node index space
#define SHB 9              // log2(NV/CH) = 512 nodes per chunk (64KB table slice)
#define CCAP 48            // per-(node,chunk) capacity (mean 16, +8 sigma)
#define NROW (NV * CH)     // 32768 bucket rows per direction

// ---- scratch (device globals; counters zero at entry: BSS on first call,
//      self-zeroed by k_mu/k_dx on every call) ----
__device__ float  g_xt  [BN];          // x,  node-major [node][batch]
__device__ float  g_fxt [BN];          // tanh(x), node-major
__device__ float  g_epst[BN];          // eps = x - mu, node-major
__device__ int    g_cF[NROW * 32];     // fwd counters, 128B padded: idx = row<<5
__device__ int    g_cB[NROW * 32];     // bwd counters
__device__ float2 g_eF[NROW * CCAP];   // fwd buckets (dst, src-chunk): (src*32, w)
__device__ float2 g_eB[NROW * CCAP];   // bwd buckets (src, dst-chunk): (dst*32, w)

// Transpose x [B,N] -> node-major, apply tanh. CTA = 1024 = 32x32 tile.
__global__ void k_prep(const float* __restrict__ x) {
    __shared__ float s[32][33];
    int tx = threadIdx.x & 31;
    int ty = threadIdx.x >> 5;
    int i0 = blockIdx.x * 32;

    s[ty][tx] = x[ty * NV + i0 + tx];          // batch-major read (coalesced)
    __syncthreads();

    float xv = s[tx][ty];
    int o = (i0 + ty) * NB + tx;               // node-major write (coalesced)
    g_xt[o]  = xv;
    g_fxt[o] = tanhf(xv);
}

// Build chunked ELL buckets; 4 edges/thread (proven shape), padded counters.
__device__ __forceinline__ void bucket_insert(int s, int d, float wt) {
    int rf = (d << 3) + (s >> SHB);
    int p  = atomicAdd(&g_cF[rf << 5], 1);
    if (p < CCAP) g_eF[rf * CCAP + p] = make_float2(__int_as_float(s << 5), wt);
    int rb = (s << 3) + (d >> SHB);
    int q  = atomicAdd(&g_cB[rb << 5], 1);
    if (q < CCAP) g_eB[rb * CCAP + q] = make_float2(__int_as_float(d << 5), wt);
}

__global__ void k_build(const float* __restrict__ w,
                        const int*   __restrict__ esrc,
                        const int*   __restrict__ edst, int E) {
    int t  = blockIdx.x * blockDim.x + threadIdx.x;
    int e0 = t << 2;
    if (e0 >= E) return;
    if (e0 + 4 <= E) {
        int4   s4 = *(const int4*)  (esrc + e0);
        int4   d4 = *(const int4*)  (edst + e0);
        float4 w4 = *(const float4*)(w    + e0);
        int rf0 = (d4.x << 3) + (s4.x >> SHB);
        int rf1 = (d4.y << 3) + (s4.y >> SHB);
        int rf2 = (d4.z << 3) + (s4.z >> SHB);
        int rf3 = (d4.w << 3) + (s4.w >> SHB);
        int rb0 = (s4.x << 3) + (d4.x >> SHB);
        int rb1 = (s4.y << 3) + (d4.y >> SHB);
        int rb2 = (s4.z << 3) + (d4.z >> SHB);
        int rb3 = (s4.w << 3) + (d4.w >> SHB);
        int p0 = atomicAdd(&g_cF[rf0 << 5], 1);
        int p1 = atomicAdd(&g_cF[rf1 << 5], 1);
        int p2 = atomicAdd(&g_cF[rf2 << 5], 1);
        int p3 = atomicAdd(&g_cF[rf3 << 5], 1);
        int q0 = atomicAdd(&g_cB[rb0 << 5], 1);
        int q1 = atomicAdd(&g_cB[rb1 << 5], 1);
        int q2 = atomicAdd(&g_cB[rb2 << 5], 1);
        int q3 = atomicAdd(&g_cB[rb3 << 5], 1);
        if (p0 < CCAP) g_eF[rf0 * CCAP + p0] = make_float2(__int_as_float(s4.x << 5), w4.x);
        if (p1 < CCAP) g_eF[rf1 * CCAP + p1] = make_float2(__int_as_float(s4.y << 5), w4.y);
        if (p2 < CCAP) g_eF[rf2 * CCAP + p2] = make_float2(__int_as_float(s4.z << 5), w4.z);
        if (p3 < CCAP) g_eF[rf3 * CCAP + p3] = make_float2(__int_as_float(s4.w << 5), w4.w);
        if (q0 < CCAP) g_eB[rb0 * CCAP + q0] = make_float2(__int_as_float(d4.x << 5), w4.x);
        if (q1 < CCAP) g_eB[rb1 * CCAP + q1] = make_float2(__int_as_float(d4.y << 5), w4.y);
        if (q2 < CCAP) g_eB[rb2 * CCAP + q2] = make_float2(__int_as_float(d4.z << 5), w4.z);
        if (q3 < CCAP) g_eB[rb3 * CCAP + q3] = make_float2(__int_as_float(d4.w << 5), w4.w);
    } else {
        for (int e = e0; e < E; e++) bucket_insert(esrc[e], edst[e], w[e]);
    }
}

// ============================================================================
// Chunked SpMM: one warp per node, 8 warps (nodes) per CTA, loop chunks 0..7.
// All warps in the CTA are barrier-aligned per chunk, so concurrent gathers on
// an SM target the same 64KB table slice -> L1-resident.
// Row staged in smem (1-2 coalesced LDG.64 per chunk), inner loop LDS.128
// broadcasts 2 edges' (colOff, w), scalar 1-line gathers, 8 in flight.
// ============================================================================
template <bool FWD>
__device__ __forceinline__ void spmm_pass(float* __restrict__ out) {
    __shared__ __align__(16) float2 srow[8][CCAP];
    int warp = threadIdx.x >> 5;
    int lane = threadIdx.x & 31;
    int node = (blockIdx.x << 3) + warp;
    const int*    cnt  = FWD ? g_cF : g_cB;
    const float2* ell  = FWD ? g_eF : g_eB;
    const float*  tabl = (FWD ? g_fxt : g_epst) + lane;

    float a0 = 0.f, a1 = 0.f, a2 = 0.f, a3 = 0.f;
    int rbase = node << 3;

    #pragma unroll
    for (int c = 0; c < CH; c++) {
        int r = rbase + c;
        int n = min(cnt[r << 5], CCAP);
        if (lane < n)      srow[warp][lane]      = ell[r * CCAP + lane];
        if (lane + 32 < n) srow[warp][lane + 32] = ell[r * CCAP + lane + 32];
        __syncwarp();

        const float4* rv = (const float4*)srow[warp];
        int npair = n >> 1;
        int p = 0;
        for (; p + 4 <= npair; p += 4) {
            float4 f0 = rv[p + 0];
            float4 f1 = rv[p + 1];
            float4 f2 = rv[p + 2];
            float4 f3 = rv[p + 3];
            float v0 = tabl[__float_as_int(f0.x)];
            float v1 = tabl[__float_as_int(f0.z)];
            float v2 = tabl[__float_as_int(f1.x)];
            float v3 = tabl[__float_as_int(f1.z)];
            float v4 = tabl[__float_as_int(f2.x)];
            float v5 = tabl[__float_as_int(f2.z)];
            float v6 = tabl[__float_as_int(f3.x)];
            float v7 = tabl[__float_as_int(f3.z)];
            a0 = fmaf(f0.y, v0, a0); a1 = fmaf(f0.w, v1, a1);
            a2 = fmaf(f1.y, v2, a2); a3 = fmaf(f1.w, v3, a3);
            a0 = fmaf(f2.y, v4, a0); a1 = fmaf(f2.w, v5, a1);
            a2 = fmaf(f3.y, v6, a2); a3 = fmaf(f3.w, v7, a3);
        }
        for (; p < npair; p++) {
            float4 f0 = rv[p];
            a0 = fmaf(f0.y, tabl[__float_as_int(f0.x)], a0);
            a1 = fmaf(f0.w, tabl[__float_as_int(f0.z)], a1);
        }
        if (n & 1) {
            float2 e0 = srow[warp][n - 1];
            a0 = fmaf(e0.y, tabl[__float_as_int(e0.x)], a0);
        }
        __syncthreads();   // chunk alignment + smem write-after-read hazard
    }

    float acc = (a0 + a1) + (a2 + a3);
    int o = (node << 5) + lane;
    if (FWD) {
        g_epst[o] = g_xt[o] - acc;
        out[lane * NV + node] = acc;                  // mu, batch-major
    } else {
        float eps = g_epst[o];
        float fx  = g_fxt[o];
        out[BN + lane * NV + node] = fmaf(fmaf(-fx, fx, 1.0f), acc, -eps);
    }
    // restore counter invariant (8 counters per node)
    if (lane < CH) {
        if (FWD) g_cF[(rbase + lane) << 5] = 0;
        else     g_cB[(rbase + lane) << 5] = 0;
    }
}

__global__ void __launch_bounds__(256, 8) k_mu(float* __restrict__ out) {
    spmm_pass<true>(out);
}

__global__ void __launch_bounds__(256, 8) k_dx(float* __restrict__ out) {
    spmm_pass<false>(out);
}

extern "C" void kernel_launch(void* const* d_in, const int* in_sizes, int n_in,
                              void* d_out, int out_size) {
    const float* x    = (const float*)d_in[0];
    const float* w    = (const float*)d_in[1];
    const int*   esrc = (const int*)d_in[2];
    const int*   edst = (const int*)d_in[3];
    float*       out  = (float*)d_out;
    int E = in_sizes[1];

    k_prep <<<NV / 32, 1024>>>(x);
    k_build<<<((E + 3) / 4 + 255) / 256, 256>>>(w, esrc, edst, E);
    k_mu   <<<NV / 8, 256>>>(out);
    k_dx   <<<NV / 8, 256>>>(out);
}

// round 10
// speedup vs baseline: 1.4205x; 1.4205x over previous
#include <cuda_runtime.h>
#include <cuda_fp16.h>

#define NV 4096            // nodes per graph
#define NB 32              // batch size (== warp size, load-bearing)
#define BN (NV * NB)       // 131072
#define CAP 256            // ELL row capacity (mean degree 128, +11 sigma headroom)
#define CSTRIDE 32         // counter padding: 1 counter per 128B line

// ---- scratch (device globals; counters zero at entry: BSS on first call,
//      self-zeroed by k_mu/k_dx on every call) ----
__device__ float  g_xt   [BN];           // x,  node-major [node][batch] (fp32)
__device__ float  g_fxt  [BN];           // tanh(x), node-major (fp32, epilogue)
__device__ __half g_fxt16[BN];           // tanh(x), node-major (fp16, gathers)
__device__ float  g_epst [BN];           // eps, node-major (fp32, epilogue)
__device__ __half g_epst16[BN];          // eps, node-major (fp16, gathers)
__device__ int    g_cnt_dst[NV * CSTRIDE];   // padded: index node*32
__device__ int    g_cnt_src[NV * CSTRIDE];
__device__ float2 g_ellF[NV * CAP];      // rows keyed by dst: (src*32, w)
__device__ float2 g_ellB[NV * CAP];      // rows keyed by src: (dst*32, w)

// Transpose x [B,N] -> node-major, apply tanh (fp32 + fp16 copies).
__global__ void k_prep(const float* __restrict__ x) {
    __shared__ float s[32][33];
    int tx = threadIdx.x & 31;
    int ty = threadIdx.x >> 5;
    int i0 = blockIdx.x * 32;

    s[ty][tx] = x[ty * NV + i0 + tx];          // batch-major read (coalesced)
    __syncthreads();

    float xv = s[tx][ty];
    float fx = tanhf(xv);
    int o = (i0 + ty) * NB + tx;               // node-major write (coalesced)
    g_xt[o]    = xv;
    g_fxt[o]   = fx;
    g_fxt16[o] = __float2half_rn(fx);
}

// Build both ELL structures; 4 edges/thread, padded counters (R6-proven).
__global__ void k_build(const float* __restrict__ w,
                        const int*   __restrict__ esrc,
                        const int*   __restrict__ edst, int E) {
    int t  = blockIdx.x * blockDim.x + threadIdx.x;
    int e0 = t << 2;
    if (e0 >= E) return;
    if (e0 + 4 <= E) {
        int4   s4 = *(const int4*)  (esrc + e0);
        int4   d4 = *(const int4*)  (edst + e0);
        float4 w4 = *(const float4*)(w    + e0);
        int p0 = atomicAdd(&g_cnt_dst[d4.x << 5], 1);
        int p1 = atomicAdd(&g_cnt_dst[d4.y << 5], 1);
        int p2 = atomicAdd(&g_cnt_dst[d4.z << 5], 1);
        int p3 = atomicAdd(&g_cnt_dst[d4.w << 5], 1);
        int q0 = atomicAdd(&g_cnt_src[s4.x << 5], 1);
        int q1 = atomicAdd(&g_cnt_src[s4.y << 5], 1);
        int q2 = atomicAdd(&g_cnt_src[s4.z << 5], 1);
        int q3 = atomicAdd(&g_cnt_src[s4.w << 5], 1);
        if (p0 < CAP) g_ellF[(d4.x << 8) + p0] = make_float2(__int_as_float(s4.x << 5), w4.x);
        if (p1 < CAP) g_ellF[(d4.y << 8) + p1] = make_float2(__int_as_float(s4.y << 5), w4.y);
        if (p2 < CAP) g_ellF[(d4.z << 8) + p2] = make_float2(__int_as_float(s4.z << 5), w4.z);
        if (p3 < CAP) g_ellF[(d4.w << 8) + p3] = make_float2(__int_as_float(s4.w << 5), w4.w);
        if (q0 < CAP) g_ellB[(s4.x << 8) + q0] = make_float2(__int_as_float(d4.x << 5), w4.x);
        if (q1 < CAP) g_ellB[(s4.y << 8) + q1] = make_float2(__int_as_float(d4.y << 5), w4.y);
        if (q2 < CAP) g_ellB[(s4.z << 8) + q2] = make_float2(__int_as_float(d4.z << 5), w4.z);
        if (q3 < CAP) g_ellB[(s4.w << 8) + q3] = make_float2(__int_as_float(d4.w << 5), w4.w);
    } else {
        for (int e = e0; e < E; e++) {
            int s = esrc[e], d = edst[e];
            float wt = w[e];
            int p = atomicAdd(&g_cnt_dst[d << 5], 1);
            if (p < CAP) g_ellF[(d << 8) + p] = make_float2(__int_as_float(s << 5), wt);
            int q = atomicAdd(&g_cnt_src[s << 5], 1);
            if (q < CAP) g_ellB[(s << 8) + q] = make_float2(__int_as_float(d << 5), wt);
        }
    }
}

// SpMM inner loop over smem-staged row [jb,je): LDS.64 broadcast of
// (colOff, w), fp16 1-sector-pair gathers via pre-offset lane pointer,
// unroll-8 for 8 gathers in flight. (R5-proven structure.)
__device__ __forceinline__ float spmm_smem(const float2* row,
                                           const __half* __restrict__ tabl,
                                           int jb, int je) {
    float a0 = 0.f, a1 = 0.f, a2 = 0.f, a3 = 0.f;
    int j = jb;
    for (; j + 8 <= je; j += 8) {
        float2 e0 = row[j + 0]; float2 e1 = row[j + 1];
        float2 e2 = row[j + 2]; float2 e3 = row[j + 3];
        float2 e4 = row[j + 4]; float2 e5 = row[j + 5];
        float2 e6 = row[j + 6]; float2 e7 = row[j + 7];
        float v0 = __half2float(tabl[__float_as_int(e0.x)]);
        float v1 = __half2float(tabl[__float_as_int(e1.x)]);
        float v2 = __half2float(tabl[__float_as_int(e2.x)]);
        float v3 = __half2float(tabl[__float_as_int(e3.x)]);
        float v4 = __half2float(tabl[__float_as_int(e4.x)]);
        float v5 = __half2float(tabl[__float_as_int(e5.x)]);
        float v6 = __half2float(tabl[__float_as_int(e6.x)]);
        float v7 = __half2float(tabl[__float_as_int(e7.x)]);
        a0 = fmaf(e0.y, v0, a0); a1 = fmaf(e1.y, v1, a1);
        a2 = fmaf(e2.y, v2, a2); a3 = fmaf(e3.y, v3, a3);
        a0 = fmaf(e4.y, v4, a0); a1 = fmaf(e5.y, v5, a1);
        a2 = fmaf(e6.y, v6, a2); a3 = fmaf(e7.y, v7, a3);
    }
    for (; j < je; j++) {
        float2 e0 = row[j];
        a0 = fmaf(e0.y, __half2float(tabl[__float_as_int(e0.x)]), a0);
    }
    return (a0 + a1) + (a2 + a3);
}

// Forward SpMM: mu = sum w * fx[src]; eps = x - mu (fp32 + fp16);
// mu written straight to out[0] batch-major (scattered 4B stores).
__global__ void __launch_bounds__(256, 8) k_mu(float* __restrict__ out) {
    __shared__ float2 srow[2][CAP];
    __shared__ float  part[2][4][32];
    int warp  = threadIdx.x >> 5;
    int lane  = threadIdx.x & 31;
    int local = warp >> 2;
    int q     = warp & 3;
    int node0 = blockIdx.x << 1;

    int n0 = min(g_cnt_dst[node0 << 5],       CAP);
    int n1 = min(g_cnt_dst[(node0 + 1) << 5], CAP);
    for (int i = threadIdx.x; i < n0; i += 256) srow[0][i] = g_ellF[(node0 << 8) + i];
    for (int i = threadIdx.x; i < n1; i += 256) srow[1][i] = g_ellF[((node0 + 1) << 8) + i];
    __syncthreads();

    int n  = local ? n1 : n0;
    int jb = (n * q) >> 2;
    int je = (n * (q + 1)) >> 2;
    const __half* tabl = g_fxt16 + lane;

    part[local][q][lane] = spmm_smem(srow[local], tabl, jb, je);
    __syncthreads();

    if (q == 0) {
        float mu = (part[local][0][lane] + part[local][1][lane])
                 + (part[local][2][lane] + part[local][3][lane]);
        int node = node0 + local;
        int o = (node << 5) + lane;
        float eps = g_xt[o] - mu;
        g_epst[o]   = eps;
        g_epst16[o] = __float2half_rn(eps);
        out[lane * NV + node] = mu;                     // batch-major, scattered
        if (lane == 0) g_cnt_dst[node << 5] = 0;        // restore invariant
    }
}

// Backward SpMM: dx = -eps + (1-fx^2) * sum w * eps[dst];
// dx written straight to out[1] batch-major.
__global__ void __launch_bounds__(256, 8) k_dx(float* __restrict__ out) {
    __shared__ float2 srow[2][CAP];
    __shared__ float  part[2][4][32];
    int warp  = threadIdx.x >> 5;
    int lane  = threadIdx.x & 31;
    int local = warp >> 2;
    int q     = warp & 3;
    int node0 = blockIdx.x << 1;

    int n0 = min(g_cnt_src[node0 << 5],       CAP);
    int n1 = min(g_cnt_src[(node0 + 1) << 5], CAP);
    for (int i = threadIdx.x; i < n0; i += 256) srow[0][i] = g_ellB[(node0 << 8) + i];
    for (int i = threadIdx.x; i < n1; i += 256) srow[1][i] = g_ellB[((node0 + 1) << 8) + i];
    __syncthreads();

    int n  = local ? n1 : n0;
    int jb = (n * q) >> 2;
    int je = (n * (q + 1)) >> 2;
    const __half* tabl = g_epst16 + lane;

    part[local][q][lane] = spmm_smem(srow[local], tabl, jb, je);
    __syncthreads();

    if (q == 0) {
        float acc = (part[local][0][lane] + part[local][1][lane])
                  + (part[local][2][lane] + part[local][3][lane]);
        int node = node0 + local;
        int o = (node << 5) + lane;
        float eps = g_epst[o];
        float fx  = g_fxt[o];
        out[BN + lane * NV + node] = fmaf(fmaf(-fx, fx, 1.0f), acc, -eps);
        if (lane == 0) g_cnt_src[node << 5] = 0;        // restore invariant
    }
}

extern "C" void kernel_launch(void* const* d_in, const int* in_sizes, int n_in,
                              void* d_out, int out_size) {
    const float* x    = (const float*)d_in[0];
    const float* w    = (const float*)d_in[1];
    const int*   esrc = (const int*)d_in[2];
    const int*   edst = (const int*)d_in[3];
    float*       out  = (float*)d_out;
    int E = in_sizes[1];

    k_prep <<<NV / 32, 1024>>>(x);
    k_build<<<((E + 3) / 4 + 255) / 256, 256>>>(w, esrc, edst, E);
    k_mu   <<<NV / 2, 256>>>(out);
    k_dx   <<<NV / 2, 256>>>(out);
}